// round 15
// baseline (speedup 1.0000x reference)
#include <cuda_runtime.h>
#include <cuda_bf16.h>
#include <math.h>

#define Bq 2
#define Nq 4096
#define Dq 512
#define Mq (Bq*Nq)
#define WIN 8
#define ROUNDS 3
#define MATSZ (512*512)

// ---------------- scratch ----------------
__device__ float g_A[Mq*Dq];
__device__ float g_C[Mq*Dq];
__device__ float g_x[Mq*Dq];                    // h + delta (pre-LN)
__device__ float g_h[Mq*Dq];
__device__ __nv_bfloat16 g_hh[Mq*Dq],  g_hl[Mq*Dq];
__device__ __nv_bfloat16 g_Gh[Mq*Dq],  g_Gl[Mq*Dq];
__device__ __nv_bfloat16 g_preh[Mq*Dq], g_prel[Mq*Dq];
__device__ __nv_bfloat16 g_Wp[6 * 2 * MATSZ];   // prepacked weights (transposed splits)
__device__ __nv_bfloat16 g_m2[2 * MATSZ];       // msg_w2 row-major split (hi|lo)
__device__ __nv_bfloat16 g_Wc[2 * MATSZ];       // Wc^T [n][k] split (hi|lo)
__device__ float g_bc[Dq];                      // folded bias

__device__ __forceinline__ float gelu_exact(float x) {
    return 0.5f * x * (1.0f + erff(x * 0.7071067811865476f));
}

#define F_ACCUM 1
#define F_BIAS  2
#define F_GELU  4
#define F_F32   8
#define F_SPLIT 16

__device__ __forceinline__ void splitpair(float a, float b, unsigned& h, unsigned& l) {
    __nv_bfloat162 hb = __float22bfloat162_rn(make_float2(a, b));
    float2 hf = __bfloat1622float2(hb);
    __nv_bfloat162 lb = __float22bfloat162_rn(make_float2(a - hf.x, b - hf.y));
    h = *(unsigned*)&hb;
    l = *(unsigned*)&lb;
}

// ---------------- weight prepack: transpose + bf16 hi/lo split ----------------
__global__ __launch_bounds__(256) void prepack_kernel(
    const float* s0, const float* s1, const float* s2,
    const float* s3, const float* s4, const float* s5,
    __nv_bfloat16* out)
{
    const float* S[6] = {s0, s1, s2, s3, s4, s5};
    int m = blockIdx.z;
    const float* src = S[m];
    __nv_bfloat16* dh = out + (size_t)m * 2 * MATSZ;
    __nv_bfloat16* dl = dh + MATSZ;

    __shared__ float t[32][33];
    int k0 = blockIdx.x * 32, n0 = blockIdx.y * 32;
    int tx = threadIdx.x & 31, ty = threadIdx.x >> 5;
    #pragma unroll
    for (int j = 0; j < 4; j++)
        t[ty + 8 * j][tx] = src[(size_t)(k0 + ty + 8 * j) * 512 + n0 + tx];
    __syncthreads();
    #pragma unroll
    for (int j = 0; j < 4; j++) {
        float v = t[tx][ty + 8 * j];
        __nv_bfloat16 h = __float2bfloat16_rn(v);
        float r = v - __bfloat162float(h);
        __nv_bfloat16 l = __float2bfloat16_rn(r);
        size_t o = (size_t)(n0 + ty + 8 * j) * 512 + k0 + tx;
        dh[o] = h;
        dl[o] = l;
    }
}

// ---------------- elementwise fp32 -> bf16 hi/lo split ----------------
__global__ __launch_bounds__(256) void split_kernel(
    const float* __restrict__ src, __nv_bfloat16* __restrict__ dh,
    __nv_bfloat16* __restrict__ dl)
{
    int idx = blockIdx.x * blockDim.x + threadIdx.x;
    float4 v = ((const float4*)src)[idx];
    unsigned h0, l0, h1, l1;
    splitpair(v.x, v.y, h0, l0);
    splitpair(v.z, v.w, h1, l1);
    uint2 hh; hh.x = h0; hh.y = h1;
    uint2 ll; ll.x = l0; ll.y = l1;
    ((uint2*)dh)[idx] = hh;
    ((uint2*)dl)[idx] = ll;
}

// ---------------- bc = upd_b1 + msg_b2 @ upd_w1b ----------------
__global__ __launch_bounds__(256) void bias_kernel(
    const float* __restrict__ b2, const float* __restrict__ w1b,
    const float* __restrict__ b1, float* __restrict__ bc)
{
    __shared__ float red[8][32];
    int nn = threadIdx.x & 31, jg = threadIdx.x >> 5;
    int n = blockIdx.x * 32 + nn;
    float acc = 0.f;
    for (int j = jg * 64; j < jg * 64 + 64; j++)
        acc += b2[j] * w1b[(size_t)j * 512 + n];
    red[jg][nn] = acc;
    __syncthreads();
    if (jg == 0) {
        float s = b1[n];
        #pragma unroll
        for (int g = 0; g < 8; g++) s += red[g][nn];
        bc[n] = s;
    }
}

// ---------------- tensor-core GEMM (bf16x3, pre-split, 3-stage) ----------------
// mt-pair interleave: same-accumulator MMA reuse distance 8 (hides tensor RAW latency).

__device__ __forceinline__ void mma_bf16(float* d, const unsigned* a, unsigned b0, unsigned b1) {
    asm volatile(
        "mma.sync.aligned.m16n8k16.row.col.f32.bf16.bf16.f32 "
        "{%0,%1,%2,%3},{%4,%5,%6,%7},{%8,%9},{%0,%1,%2,%3};\n"
        : "+f"(d[0]), "+f"(d[1]), "+f"(d[2]), "+f"(d[3])
        : "r"(a[0]), "r"(a[1]), "r"(a[2]), "r"(a[3]), "r"(b0), "r"(b1));
}
__device__ __forceinline__ void cp16(unsigned saddr, const void* g) {
    asm volatile("cp.async.cg.shared.global [%0], [%1], 16;\n" :: "r"(saddr), "l"(g));
}
__device__ __forceinline__ void ldsm4(unsigned* r, unsigned addr) {
    asm volatile("ldmatrix.sync.aligned.m8n8.x4.shared.b16 {%0,%1,%2,%3}, [%4];\n"
        : "=r"(r[0]), "=r"(r[1]), "=r"(r[2]), "=r"(r[3]) : "r"(addr));
}

// smem: A buf b at b*16384 (128 rows x 128B: 32 hi | 32 lo bf16, chunk-XOR swizzle)
//       B buf b at 49152 + b*20480 bytes: plane*10240 + n*80 + p*4 (stride 20 u32)
#define SMEM_BYTES (49152 + 3*20480)

__global__ __launch_bounds__(256, 2) void gemm_tc(
    const __nv_bfloat16* __restrict__ Xh, const __nv_bfloat16* __restrict__ Xl,
    const __nv_bfloat16* __restrict__ Xh2, const __nv_bfloat16* __restrict__ Xl2,
    const __nv_bfloat16* __restrict__ W0, const __nv_bfloat16* __restrict__ W1,
    const __nv_bfloat16* __restrict__ Wb,
    float* __restrict__ Y0, float* __restrict__ Y1,
    __nv_bfloat16* __restrict__ Yh, __nv_bfloat16* __restrict__ Yl,
    const float* __restrict__ accsrc, const float* __restrict__ bias, int flagsw, int kts)
{
    extern __shared__ char smemc[];
    const int tid  = threadIdx.x;
    const int lane = tid & 31;
    const int warp = tid >> 5;
    const int wm   = warp & 1;
    const int wn   = warp >> 1;
    const int xa   = lane >> 2;
    const int ql   = lane & 3;

    const int seg   = blockIdx.x >> 2;
    const int ncol0 = (blockIdx.x & 3) * 128;
    const int m0    = blockIdx.y * 128;

    if (seg == 2 && blockIdx.y >= 4) return;   // Wc fold: only 512 rows (uniform per block)

    const int flags = (seg == 2) ? ((flagsw >> 8) & 0xff) : (flagsw & 0xff);

    const __nv_bfloat16* Xsh = (seg == 2) ? Xh2 : Xh;
    const __nv_bfloat16* Xsl = (seg == 2) ? Xl2 : Xl;
    const __nv_bfloat16* W = (seg == 2) ? Wb : (seg ? W1 : W0);
    float*               Y = seg ? Y1 : Y0;

    unsigned sbase = (unsigned)__cvta_generic_to_shared(smemc);

    float acc[4][4][4];
    #pragma unroll
    for (int a = 0; a < 4; a++)
        #pragma unroll
        for (int b = 0; b < 4; b++)
            #pragma unroll
            for (int c = 0; c < 4; c++) acc[a][b][c] = 0.f;

    const __nv_bfloat16* XhB  = Xsh + (size_t)m0 * Dq;
    const __nv_bfloat16* XlB  = Xsl + (size_t)m0 * Dq;
    const __nv_bfloat16* XhB2 = Xh2 + (size_t)m0 * Dq;
    const __nv_bfloat16* XlB2 = Xl2 + (size_t)m0 * Dq;
    const __nv_bfloat16* Whi  = W + (size_t)ncol0 * Dq;
    const __nv_bfloat16* Wlo  = W + MATSZ + (size_t)ncol0 * Dq;
    const __nv_bfloat16* Whi2 = Wb + (size_t)ncol0 * Dq;
    const __nv_bfloat16* Wlo2 = Wb + MATSZ + (size_t)ncol0 * Dq;

    auto load_tile = [&](int kt, int buf) {
        const __nv_bfloat16 *xh, *xl, *wh, *wl;
        int kpos;
        if (kt < 16) { xh = XhB;  xl = XlB;  wh = Whi;  wl = Wlo;  kpos = kt * 32; }
        else         { xh = XhB2; xl = XlB2; wh = Whi2; wl = Wlo2; kpos = (kt - 16) * 32; }
        unsigned ab = sbase + (unsigned)buf * 16384u;
        unsigned bb = sbase + 49152u + (unsigned)buf * 20480u;
        #pragma unroll
        for (int i = 0; i < 4; i++) {
            int id = tid + i * 256;
            int row = id >> 3, ch = id & 7;
            const __nv_bfloat16* pl = (ch < 4) ? xh : xl;
            cp16(ab + (unsigned)(row * 128 + ((ch ^ (row & 7)) << 4)),
                 pl + (size_t)row * Dq + kpos + (ch & 3) * 8);
        }
        #pragma unroll
        for (int i = 0; i < 4; i++) {
            int idx = tid + i * 256;
            int half = idx >> 9, n = (idx >> 2) & 127, ch = idx & 3;
            const __nv_bfloat16* src = (half ? wl : wh) + (size_t)n * Dq + kpos + ch * 8;
            cp16(bb + (unsigned)(half * 10240 + n * 80 + ch * 16), src);
        }
    };

    load_tile(0, 0);
    asm volatile("cp.async.commit_group;\n");
    load_tile(1, 1);
    asm volatile("cp.async.commit_group;\n");

    // per-lane ldmatrix invariants
    const int rowl  = (lane & 7) + ((lane >> 3) & 1) * 8;   // A: 0..15
    const int choff = lane >> 4;                            // A: 0..1
    const int r7    = rowl & 7;
    const unsigned bO = (unsigned)((wn * 32 + ((lane >> 4) & 1) * 8 + (lane & 7)) * 80
                                   + ((lane >> 3) & 1) * 16);

    #pragma unroll 1
    for (int kt = 0; kt < kts; kt++) {
        asm volatile("cp.async.wait_group 1;\n");
        __syncthreads();
        if (kt + 2 < kts) load_tile(kt + 2, (kt + 2) % 3);
        asm volatile("cp.async.commit_group;\n");

        const int buf = kt % 3;
        const unsigned abase = sbase + (unsigned)buf * 16384u;
        const unsigned bbase = sbase + 49152u + (unsigned)buf * 20480u;

        #pragma unroll
        for (int s = 0; s < 2; s++) {
            unsigned bh[4][2], bl[4][2];
            #pragma unroll
            for (int ntp = 0; ntp < 2; ntp++) {
                unsigned r[4];
                ldsm4(r, bbase + (unsigned)(ntp * 1280 + s * 32) + bO);
                bh[ntp * 2][0] = r[0]; bh[ntp * 2][1] = r[1];
                bh[ntp * 2 + 1][0] = r[2]; bh[ntp * 2 + 1][1] = r[3];
                ldsm4(r, bbase + 10240u + (unsigned)(ntp * 1280 + s * 32) + bO);
                bl[ntp * 2][0] = r[0]; bl[ntp * 2][1] = r[1];
                bl[ntp * 2 + 1][0] = r[2]; bl[ntp * 2 + 1][1] = r[3];
            }
            const unsigned swh = (unsigned)(((0 + s * 2 + choff) ^ r7) << 4);
            const unsigned swl = (unsigned)(((4 + s * 2 + choff) ^ r7) << 4);
            // mt-pair interleave: fragments for two m-tiles, then 24 MMAs with
            // same-accumulator reuse distance of 8 instructions.
            #pragma unroll
            for (int mp = 0; mp < 2; mp++) {
                const int mt0 = mp * 2, mt1 = mp * 2 + 1;
                unsigned rb0 = (unsigned)((wm * 64 + mt0 * 16 + rowl) * 128);
                unsigned rb1 = (unsigned)((wm * 64 + mt1 * 16 + rowl) * 128);
                unsigned ah0[4], al0[4], ah1[4], al1[4];
                ldsm4(ah0, abase + rb0 + swh);
                ldsm4(al0, abase + rb0 + swl);
                ldsm4(ah1, abase + rb1 + swh);
                ldsm4(al1, abase + rb1 + swl);
                #pragma unroll
                for (int nt = 0; nt < 4; nt++) mma_bf16(acc[mt0][nt], ah0, bh[nt][0], bh[nt][1]);
                #pragma unroll
                for (int nt = 0; nt < 4; nt++) mma_bf16(acc[mt1][nt], ah1, bh[nt][0], bh[nt][1]);
                #pragma unroll
                for (int nt = 0; nt < 4; nt++) mma_bf16(acc[mt0][nt], ah0, bl[nt][0], bl[nt][1]);
                #pragma unroll
                for (int nt = 0; nt < 4; nt++) mma_bf16(acc[mt1][nt], ah1, bl[nt][0], bl[nt][1]);
                #pragma unroll
                for (int nt = 0; nt < 4; nt++) mma_bf16(acc[mt0][nt], al0, bh[nt][0], bh[nt][1]);
                #pragma unroll
                for (int nt = 0; nt < 4; nt++) mma_bf16(acc[mt1][nt], al1, bh[nt][0], bh[nt][1]);
            }
        }
    }

    // ---- epilogue ----
    const int row0 = m0 + wm * 64;
    const int colg = ncol0 + (wn << 5);
    #pragma unroll
    for (int mt = 0; mt < 4; mt++) {
        #pragma unroll
        for (int nt = 0; nt < 4; nt++) {
            int r = row0 + mt * 16 + xa;
            int c = colg + nt * 8 + ql * 2;
            float v00 = acc[mt][nt][0], v01 = acc[mt][nt][1];
            float v10 = acc[mt][nt][2], v11 = acc[mt][nt][3];
            if (flags & F_ACCUM) {
                float2 e0 = *(const float2*)(accsrc + (size_t)r * Dq + c);
                float2 e1 = *(const float2*)(accsrc + (size_t)(r + 8) * Dq + c);
                v00 += e0.x; v01 += e0.y; v10 += e1.x; v11 += e1.y;
            }
            if (flags & F_BIAS) {
                float2 bb = *(const float2*)(bias + c);
                v00 += bb.x; v01 += bb.y; v10 += bb.x; v11 += bb.y;
            }
            if (flags & F_GELU) {
                v00 = gelu_exact(v00); v01 = gelu_exact(v01);
                v10 = gelu_exact(v10); v11 = gelu_exact(v11);
            }
            if (flags & F_F32) {
                float2 o0; o0.x = v00; o0.y = v01;
                float2 o1; o1.x = v10; o1.y = v11;
                *(float2*)(Y + (size_t)r * Dq + c) = o0;
                *(float2*)(Y + (size_t)(r + 8) * Dq + c) = o1;
            }
            if (flags & F_SPLIT) {
                unsigned h0, l0, h1, l1;
                splitpair(v00, v01, h0, l0);
                splitpair(v10, v11, h1, l1);
                *(unsigned*)(Yh + (size_t)r * Dq + c) = h0;
                *(unsigned*)(Yl + (size_t)r * Dq + c) = l0;
                *(unsigned*)(Yh + (size_t)(r + 8) * Dq + c) = h1;
                *(unsigned*)(Yl + (size_t)(r + 8) * Dq + c) = l1;
            }
        }
    }
}

// ------- G_i = (1/cnt_i) * sum_{off} gelu(A_i + C_{i-off} + b1); bf16 hi/lo out -------
__global__ __launch_bounds__(256) void gelu_sum_kernel(
    const float* __restrict__ A, const float* __restrict__ Cc,
    const float* __restrict__ b1,
    __nv_bfloat16* __restrict__ Gh, __nv_bfloat16* __restrict__ Gl)
{
    int gid = blockIdx.x * blockDim.x + threadIdx.x;  // [0, Mq*64)
    int row = gid >> 6;
    int c8  = gid & 63;
    int i   = row & (Nq - 1);
    int nvalid = (i < WIN ? i : WIN) + 1;

    int idx4 = row * 128 + c8 * 2;
    float4 a0 = ((const float4*)A)[idx4];
    float4 a1 = ((const float4*)A)[idx4 + 1];
    float4 b0v = ((const float4*)b1)[c8 * 2];
    float4 b1v = ((const float4*)b1)[c8 * 2 + 1];
    a0.x += b0v.x; a0.y += b0v.y; a0.z += b0v.z; a0.w += b0v.w;
    a1.x += b1v.x; a1.y += b1v.y; a1.z += b1v.z; a1.w += b1v.w;

    float s0 = 0.f, s1 = 0.f, s2 = 0.f, s3 = 0.f;
    float s4 = 0.f, s5 = 0.f, s6 = 0.f, s7 = 0.f;
    const float4* Cp = (const float4*)Cc + idx4;
    for (int off = 0; off < nvalid; off++) {
        float4 c0 = Cp[0];
        float4 c1 = Cp[1];
        Cp -= 128;
        s0 += gelu_exact(a0.x + c0.x);
        s1 += gelu_exact(a0.y + c0.y);
        s2 += gelu_exact(a0.z + c0.z);
        s3 += gelu_exact(a0.w + c0.w);
        s4 += gelu_exact(a1.x + c1.x);
        s5 += gelu_exact(a1.y + c1.y);
        s6 += gelu_exact(a1.z + c1.z);
        s7 += gelu_exact(a1.w + c1.w);
    }
    float inv = 1.0f / (float)nvalid;
    unsigned h0, l0, h1, l1, h2, l2, h3, l3;
    splitpair(s0 * inv, s1 * inv, h0, l0);
    splitpair(s2 * inv, s3 * inv, h1, l1);
    splitpair(s4 * inv, s5 * inv, h2, l2);
    splitpair(s6 * inv, s7 * inv, h3, l3);
    uint4 hv; hv.x = h0; hv.y = h1; hv.z = h2; hv.w = h3;
    uint4 lv; lv.x = l0; lv.y = l1; lv.z = l2; lv.w = l3;
    ((uint4*)Gh)[gid] = hv;
    ((uint4*)Gl)[gid] = lv;
}

// ------------- out = LayerNorm(x) * g + b  (+ optional bf16 split) -------------
__global__ __launch_bounds__(128) void add_ln_kernel(
    const float* __restrict__ xin,
    const float* __restrict__ gw, const float* __restrict__ bw,
    float* __restrict__ out,
    __nv_bfloat16* __restrict__ outh, __nv_bfloat16* __restrict__ outl)
{
    int row = blockIdx.x;
    int t = threadIdx.x;
    float4 xv = ((const float4*)(xin + (size_t)row * Dq))[t];
    float x0 = xv.x, x1 = xv.y, x2 = xv.z, x3 = xv.w;

    float s  = x0 + x1 + x2 + x3;
    float ss = x0 * x0 + x1 * x1 + x2 * x2 + x3 * x3;
    #pragma unroll
    for (int o = 16; o > 0; o >>= 1) {
        s  += __shfl_xor_sync(0xffffffff, s,  o);
        ss += __shfl_xor_sync(0xffffffff, ss, o);
    }
    __shared__ float sums[4], ssums[4];
    int w = t >> 5;
    if ((t & 31) == 0) { sums[w] = s; ssums[w] = ss; }
    __syncthreads();
    float stot  = sums[0]  + sums[1]  + sums[2]  + sums[3];
    float sstot = ssums[0] + ssums[1] + ssums[2] + ssums[3];
    float mu   = stot * (1.0f / Dq);
    float var  = sstot * (1.0f / Dq) - mu * mu;
    float rstd = rsqrtf(var + 1e-5f);

    float4 gv = ((const float4*)gw)[t];
    float4 bv = ((const float4*)bw)[t];
    float4 o;
    o.x = (x0 - mu) * rstd * gv.x + bv.x;
    o.y = (x1 - mu) * rstd * gv.y + bv.y;
    o.z = (x2 - mu) * rstd * gv.z + bv.z;
    o.w = (x3 - mu) * rstd * gv.w + bv.w;
    ((float4*)(out + (size_t)row * Dq))[t] = o;
    if (outh) {
        unsigned h0, l0, h1, l1;
        splitpair(o.x, o.y, h0, l0);
        splitpair(o.z, o.w, h1, l1);
        size_t idx = (size_t)row * (Dq / 4) + t;
        uint2 hh; hh.x = h0; hh.y = h1;
        uint2 ll; ll.x = l0; ll.y = l1;
        ((uint2*)outh)[idx] = hh;
        ((uint2*)outl)[idx] = ll;
    }
}

// ---------------------------------------------------------------------------------
extern "C" void kernel_launch(void* const* d_in, const int* in_sizes, int n_in,
                              void* d_out, int out_size)
{
    const float* cs     = (const float*)d_in[0];
    const float* msg_w1 = (const float*)d_in[1];
    const float* msg_b1 = (const float*)d_in[2];
    const float* msg_w2 = (const float*)d_in[3];
    const float* msg_b2 = (const float*)d_in[4];
    const float* upd_w1 = (const float*)d_in[5];
    const float* upd_b1 = (const float*)d_in[6];
    const float* upd_w2 = (const float*)d_in[7];
    const float* upd_b2 = (const float*)d_in[8];
    const float* ln_g   = (const float*)d_in[9];
    const float* ln_b   = (const float*)d_in[10];

    float *A = 0, *C = 0, *x = 0, *h = 0, *bc = 0;
    __nv_bfloat16 *hh = 0, *hl = 0, *Gh = 0, *Gl = 0,
                  *preh = 0, *prel = 0, *Wp = 0, *m2 = 0, *Wc = 0;
    if (cudaGetSymbolAddress((void**)&A,     g_A)     != cudaSuccess) return;
    if (cudaGetSymbolAddress((void**)&C,     g_C)     != cudaSuccess) return;
    if (cudaGetSymbolAddress((void**)&x,     g_x)     != cudaSuccess) return;
    if (cudaGetSymbolAddress((void**)&h,     g_h)     != cudaSuccess) return;
    if (cudaGetSymbolAddress((void**)&bc,    g_bc)    != cudaSuccess) return;
    if (cudaGetSymbolAddress((void**)&hh,    g_hh)    != cudaSuccess) return;
    if (cudaGetSymbolAddress((void**)&hl,    g_hl)    != cudaSuccess) return;
    if (cudaGetSymbolAddress((void**)&Gh,    g_Gh)    != cudaSuccess) return;
    if (cudaGetSymbolAddress((void**)&Gl,    g_Gl)    != cudaSuccess) return;
    if (cudaGetSymbolAddress((void**)&preh,  g_preh)  != cudaSuccess) return;
    if (cudaGetSymbolAddress((void**)&prel,  g_prel)  != cudaSuccess) return;
    if (cudaGetSymbolAddress((void**)&Wp,    g_Wp)    != cudaSuccess) return;
    if (cudaGetSymbolAddress((void**)&m2,    g_m2)    != cudaSuccess) return;
    if (cudaGetSymbolAddress((void**)&Wc,    g_Wc)    != cudaSuccess) return;

    cudaFuncSetAttribute(gemm_tc, cudaFuncAttributeMaxDynamicSharedMemorySize, SMEM_BYTES);

    // transposed splits: 0=msg_w1a 1=msg_w1b 2=msg_w2(unused) 3=upd_w1a 4=upd_w1b 5=upd_w2
    prepack_kernel<<<dim3(16, 16, 6), 256>>>(
        msg_w1, msg_w1 + MATSZ, msg_w2, upd_w1, upd_w1 + MATSZ, upd_w2, Wp);

    const __nv_bfloat16* Wm1a = Wp + (size_t)0 * 2 * MATSZ;
    const __nv_bfloat16* Wm1b = Wp + (size_t)1 * 2 * MATSZ;
    const __nv_bfloat16* Wu1a = Wp + (size_t)3 * 2 * MATSZ;
    const __nv_bfloat16* Wu1b = Wp + (size_t)4 * 2 * MATSZ;
    const __nv_bfloat16* Wu2  = Wp + (size_t)5 * 2 * MATSZ;

    // row-major split of msg_w2 (hi | lo)
    split_kernel<<<MATSZ / 4 / 256, 256>>>(msg_w2, m2, m2 + MATSZ);
    // bc = upd_b1 + msg_b2 @ upd_w1b
    bias_kernel<<<16, 256>>>(msg_b2, upd_w1 + MATSZ, upd_b1, bc);
    // initial split of cs into h planes
    split_kernel<<<(Mq * Dq / 4) / 256, 256>>>(cs, hh, hl);

    dim3 blk(256);
    int gs_blocks = (Mq * 64) / 256;   // 8 floats per thread

    for (int r = 0; r < ROUNDS; r++) {
        const float* hin = (r == 0) ? cs : h;
        float* hout = (r == ROUNDS - 1) ? (float*)d_out : h;

        if (r == 0) {
            // fused: A = h@msg_w1a ; C = h@msg_w1b ; seg2: Wc = split(upd_w1b^T @ msg_w2^T)
            gemm_tc<<<dim3(12, 64), blk, SMEM_BYTES>>>(hh, hl, Wu1b, Wu1b + MATSZ,
                Wm1a, Wm1b, m2, A, C, Wc, Wc + MATSZ,
                nullptr, nullptr, F_F32 | (F_SPLIT << 8), 16);
        } else {
            gemm_tc<<<dim3(8, 64), blk, SMEM_BYTES>>>(hh, hl, nullptr, nullptr,
                Wm1a, Wm1b, nullptr, A, C, nullptr, nullptr,
                nullptr, nullptr, F_F32, 16);
        }

        // G planes = split((1/cnt) * sum_off gelu(A + C_shift + b1))
        gelu_sum_kernel<<<gs_blocks, 256>>>(A, C, msg_b1, Gh, Gl);

        // pre planes = split(gelu([G|h] @ [Wc;upd_w1a] + bc))   K=1024
        gemm_tc<<<dim3(4, 64), blk, SMEM_BYTES>>>(Gh, Gl, hh, hl,
            Wc, nullptr, Wu1a, nullptr, nullptr,
            preh, prel, nullptr, bc, F_BIAS | F_GELU | F_SPLIT, 32);

        // x = h + pre @ upd_w2 + b2   (residual fused into epilogue)
        gemm_tc<<<dim3(4, 64), blk, SMEM_BYTES>>>(preh, prel, nullptr, nullptr,
            Wu2, nullptr, nullptr, x, nullptr,
            nullptr, nullptr, hin, upd_b2, F_ACCUM | F_BIAS | F_F32, 16);

        // h_out = LayerNorm(x)
        if (r == ROUNDS - 1)
            add_ln_kernel<<<Mq, 128>>>(x, ln_g, ln_b, hout, nullptr, nullptr);
        else
            add_ln_kernel<<<Mq, 128>>>(x, ln_g, ln_b, hout, hh, hl);
    }
}

// round 17
// speedup vs baseline: 1.3386x; 1.3386x over previous
#include <cuda_runtime.h>
#include <cuda_fp16.h>
#include <math.h>

#define Bq 2
#define Nq 4096
#define Dq 512
#define Mq (Bq*Nq)
#define WIN 8
#define ROUNDS 3
#define MATSZ (512*512)

// ---------------- scratch ----------------
__device__ float g_A[Mq*Dq];
__device__ float g_C[Mq*Dq];
__device__ float g_x[Mq*Dq];
__device__ float g_h[Mq*Dq];
__device__ __half g_hh[Mq*Dq],  g_hl[Mq*Dq];
__device__ __half g_Gh[Mq*Dq],  g_Gl[Mq*Dq];
__device__ __half g_preh[Mq*Dq], g_prel[Mq*Dq];
__device__ __half g_Wp[6 * 2 * MATSZ];   // prepacked weights (transposed fp16 hi|lo pairs)
__device__ __half g_m2[2 * MATSZ];       // msg_w2 row-major fp16 (hi|lo; hi used)
__device__ __half g_Wc[2 * MATSZ];       // Wc^T [n][k] fp16 (hi|lo; hi used as weight)
__device__ float g_bc[Dq];

__device__ __forceinline__ float gelu_exact(float x) {
    return 0.5f * x * (1.0f + erff(x * 0.7071067811865476f));
}

#define F_ACCUM 1
#define F_BIAS  2
#define F_GELU  4
#define F_F32   8
#define F_SPLIT 16

// fp16 hi/lo split of a float pair (22-bit combined)
__device__ __forceinline__ void splitpair(float a, float b, unsigned& h, unsigned& l) {
    __half2 hb = __float22half2_rn(make_float2(a, b));
    float2 hf = __half22float2(hb);
    __half2 lb = __float22half2_rn(make_float2(a - hf.x, b - hf.y));
    h = *(unsigned*)&hb;
    l = *(unsigned*)&lb;
}

// ---------------- weight prepack: transpose + fp16 hi/lo split ----------------
__global__ __launch_bounds__(256) void prepack_kernel(
    const float* s0, const float* s1, const float* s2,
    const float* s3, const float* s4, const float* s5,
    __half* out)
{
    const float* S[6] = {s0, s1, s2, s3, s4, s5};
    int m = blockIdx.z;
    const float* src = S[m];
    __half* dh = out + (size_t)m * 2 * MATSZ;
    __half* dl = dh + MATSZ;

    __shared__ float t[32][33];
    int k0 = blockIdx.x * 32, n0 = blockIdx.y * 32;
    int tx = threadIdx.x & 31, ty = threadIdx.x >> 5;
    #pragma unroll
    for (int j = 0; j < 4; j++)
        t[ty + 8 * j][tx] = src[(size_t)(k0 + ty + 8 * j) * 512 + n0 + tx];
    __syncthreads();
    #pragma unroll
    for (int j = 0; j < 4; j++) {
        float v = t[tx][ty + 8 * j];
        __half h = __float2half_rn(v);
        float r = v - __half2float(h);
        __half l = __float2half_rn(r);
        size_t o = (size_t)(n0 + ty + 8 * j) * 512 + k0 + tx;
        dh[o] = h;
        dl[o] = l;
    }
}

// ---------------- elementwise fp32 -> fp16 hi/lo split ----------------
__global__ __launch_bounds__(256) void split_kernel(
    const float* __restrict__ src, __half* __restrict__ dh,
    __half* __restrict__ dl)
{
    int idx = blockIdx.x * blockDim.x + threadIdx.x;
    float4 v = ((const float4*)src)[idx];
    unsigned h0, l0, h1, l1;
    splitpair(v.x, v.y, h0, l0);
    splitpair(v.z, v.w, h1, l1);
    uint2 hh; hh.x = h0; hh.y = h1;
    uint2 ll; ll.x = l0; ll.y = l1;
    ((uint2*)dh)[idx] = hh;
    ((uint2*)dl)[idx] = ll;
}

// ---------------- bc = upd_b1 + msg_b2 @ upd_w1b ----------------
__global__ __launch_bounds__(256) void bias_kernel(
    const float* __restrict__ b2, const float* __restrict__ w1b,
    const float* __restrict__ b1, float* __restrict__ bc)
{
    __shared__ float red[8][32];
    int nn = threadIdx.x & 31, jg = threadIdx.x >> 5;
    int n = blockIdx.x * 32 + nn;
    float acc = 0.f;
    for (int j = jg * 64; j < jg * 64 + 64; j++)
        acc += b2[j] * w1b[(size_t)j * 512 + n];
    red[jg][nn] = acc;
    __syncthreads();
    if (jg == 0) {
        float s = b1[n];
        #pragma unroll
        for (int g = 0; g < 8; g++) s += red[g][nn];
        bc[n] = s;
    }
}

// ---------------- tensor-core GEMM (fp16 2-pass: X hi/lo planes x single-fp16 W) ----------------
// Y[M x 512] = X @ W^T (+ optional second K-half X2 @ Wb^T when kts=32);
// seg 2 (grid.x=12, kts=16): X=Xh2/Xl2, W=Wb, flags from high byte (Wc fold).

__device__ __forceinline__ void mma_f16(float* d, const unsigned* a, unsigned b0, unsigned b1) {
    asm volatile(
        "mma.sync.aligned.m16n8k16.row.col.f32.f16.f16.f32 "
        "{%0,%1,%2,%3},{%4,%5,%6,%7},{%8,%9},{%0,%1,%2,%3};\n"
        : "+f"(d[0]), "+f"(d[1]), "+f"(d[2]), "+f"(d[3])
        : "r"(a[0]), "r"(a[1]), "r"(a[2]), "r"(a[3]), "r"(b0), "r"(b1));
}
__device__ __forceinline__ void cp16(unsigned saddr, const void* g) {
    asm volatile("cp.async.cg.shared.global [%0], [%1], 16;\n" :: "r"(saddr), "l"(g));
}
__device__ __forceinline__ void ldsm4(unsigned* r, unsigned addr) {
    asm volatile("ldmatrix.sync.aligned.m8n8.x4.shared.b16 {%0,%1,%2,%3}, [%4];\n"
        : "=r"(r[0]), "=r"(r[1]), "=r"(r[2]), "=r"(r[3]) : "r"(addr));
}

// smem: A buf b at b*16384 (128 rows x 128B: 32 hi | 32 lo fp16, chunk-XOR swizzle)
//       B buf b at 49152 + b*10240 bytes: n*80 + ch*16 (stride 20 u32, single plane)
#define SMEM_BYTES (49152 + 3*10240)

__global__ __launch_bounds__(256, 2) void gemm_tc(
    const __half* __restrict__ Xh, const __half* __restrict__ Xl,
    const __half* __restrict__ Xh2, const __half* __restrict__ Xl2,
    const __half* __restrict__ W0, const __half* __restrict__ W1,
    const __half* __restrict__ Wb,
    float* __restrict__ Y0, float* __restrict__ Y1,
    __half* __restrict__ Yh, __half* __restrict__ Yl,
    const float* __restrict__ accsrc, const float* __restrict__ bias, int flagsw, int kts)
{
    extern __shared__ char smemc[];
    const int tid  = threadIdx.x;
    const int lane = tid & 31;
    const int warp = tid >> 5;
    const int wm   = warp & 1;
    const int wn   = warp >> 1;
    const int xa   = lane >> 2;
    const int ql   = lane & 3;

    const int seg   = blockIdx.x >> 2;
    const int ncol0 = (blockIdx.x & 3) * 128;
    const int m0    = blockIdx.y * 128;

    if (seg == 2 && blockIdx.y >= 4) return;   // Wc fold: only 512 rows (uniform per block)

    const int flags = (seg == 2) ? ((flagsw >> 8) & 0xff) : (flagsw & 0xff);

    const __half* Xsh = (seg == 2) ? Xh2 : Xh;
    const __half* Xsl = (seg == 2) ? Xl2 : Xl;
    const __half* W = (seg == 2) ? Wb : (seg ? W1 : W0);
    float*        Y = seg ? Y1 : Y0;

    unsigned sbase = (unsigned)__cvta_generic_to_shared(smemc);

    float acc[4][4][4];
    #pragma unroll
    for (int a = 0; a < 4; a++)
        #pragma unroll
        for (int b = 0; b < 4; b++)
            #pragma unroll
            for (int c = 0; c < 4; c++) acc[a][b][c] = 0.f;

    const __half* XhB  = Xsh + (size_t)m0 * Dq;
    const __half* XlB  = Xsl + (size_t)m0 * Dq;
    const __half* XhB2 = Xh2 + (size_t)m0 * Dq;
    const __half* XlB2 = Xl2 + (size_t)m0 * Dq;
    const __half* Wcur  = W + (size_t)ncol0 * Dq;
    const __half* Wcur2 = Wb + (size_t)ncol0 * Dq;

    auto load_tile = [&](int kt, int buf) {
        const __half *xh, *xl, *wv;
        int kpos;
        if (kt < 16) { xh = XhB;  xl = XlB;  wv = Wcur;  kpos = kt * 32; }
        else         { xh = XhB2; xl = XlB2; wv = Wcur2; kpos = (kt - 16) * 32; }
        unsigned ab = sbase + (unsigned)buf * 16384u;
        unsigned bb = sbase + 49152u + (unsigned)buf * 10240u;
        #pragma unroll
        for (int i = 0; i < 4; i++) {
            int id = tid + i * 256;
            int row = id >> 3, ch = id & 7;
            const __half* pl = (ch < 4) ? xh : xl;
            cp16(ab + (unsigned)(row * 128 + ((ch ^ (row & 7)) << 4)),
                 pl + (size_t)row * Dq + kpos + (ch & 3) * 8);
        }
        #pragma unroll
        for (int i = 0; i < 2; i++) {
            int idx = tid + i * 256;
            int n = idx >> 2, ch = idx & 3;
            cp16(bb + (unsigned)(n * 80 + ch * 16),
                 wv + (size_t)n * Dq + kpos + ch * 8);
        }
    };

    load_tile(0, 0);
    asm volatile("cp.async.commit_group;\n");
    load_tile(1, 1);
    asm volatile("cp.async.commit_group;\n");

    // per-lane ldmatrix invariants
    const int rowl  = (lane & 7) + ((lane >> 3) & 1) * 8;   // A: 0..15
    const int choff = lane >> 4;                            // A: 0..1
    const int r7    = rowl & 7;
    const unsigned bO = (unsigned)((wn * 32 + ((lane >> 4) & 1) * 8 + (lane & 7)) * 80
                                   + ((lane >> 3) & 1) * 16);

    #pragma unroll 1
    for (int kt = 0; kt < kts; kt++) {
        asm volatile("cp.async.wait_group 1;\n");
        __syncthreads();
        if (kt + 2 < kts) load_tile(kt + 2, (kt + 2) % 3);
        asm volatile("cp.async.commit_group;\n");

        const int buf = kt % 3;
        const unsigned abase = sbase + (unsigned)buf * 16384u;
        const unsigned bbase = sbase + 49152u + (unsigned)buf * 10240u;

        #pragma unroll
        for (int s = 0; s < 2; s++) {
            unsigned bh[4][2];
            #pragma unroll
            for (int ntp = 0; ntp < 2; ntp++) {
                unsigned r[4];
                ldsm4(r, bbase + (unsigned)(ntp * 1280 + s * 32) + bO);
                bh[ntp * 2][0] = r[0]; bh[ntp * 2][1] = r[1];
                bh[ntp * 2 + 1][0] = r[2]; bh[ntp * 2 + 1][1] = r[3];
            }
            const unsigned swh = (unsigned)(((0 + s * 2 + choff) ^ r7) << 4);
            const unsigned swl = (unsigned)(((4 + s * 2 + choff) ^ r7) << 4);
            #pragma unroll
            for (int mt = 0; mt < 4; mt++) {
                unsigned rbyte = (unsigned)((wm * 64 + mt * 16 + rowl) * 128);
                unsigned ah[4], al[4];
                ldsm4(ah, abase + rbyte + swh);
                ldsm4(al, abase + rbyte + swl);
                #pragma unroll
                for (int nt = 0; nt < 4; nt++) mma_f16(acc[mt][nt], ah, bh[nt][0], bh[nt][1]);
                #pragma unroll
                for (int nt = 0; nt < 4; nt++) mma_f16(acc[mt][nt], al, bh[nt][0], bh[nt][1]);
            }
        }
    }

    // ---- epilogue ----
    const int row0 = m0 + wm * 64;
    const int colg = ncol0 + (wn << 5);
    #pragma unroll
    for (int mt = 0; mt < 4; mt++) {
        #pragma unroll
        for (int nt = 0; nt < 4; nt++) {
            int r = row0 + mt * 16 + xa;
            int c = colg + nt * 8 + ql * 2;
            float v00 = acc[mt][nt][0], v01 = acc[mt][nt][1];
            float v10 = acc[mt][nt][2], v11 = acc[mt][nt][3];
            if (flags & F_ACCUM) {
                float2 e0 = *(const float2*)(accsrc + (size_t)r * Dq + c);
                float2 e1 = *(const float2*)(accsrc + (size_t)(r + 8) * Dq + c);
                v00 += e0.x; v01 += e0.y; v10 += e1.x; v11 += e1.y;
            }
            if (flags & F_BIAS) {
                float2 bb = *(const float2*)(bias + c);
                v00 += bb.x; v01 += bb.y; v10 += bb.x; v11 += bb.y;
            }
            if (flags & F_GELU) {
                v00 = gelu_exact(v00); v01 = gelu_exact(v01);
                v10 = gelu_exact(v10); v11 = gelu_exact(v11);
            }
            if (flags & F_F32) {
                float2 o0; o0.x = v00; o0.y = v01;
                float2 o1; o1.x = v10; o1.y = v11;
                *(float2*)(Y + (size_t)r * Dq + c) = o0;
                *(float2*)(Y + (size_t)(r + 8) * Dq + c) = o1;
            }
            if (flags & F_SPLIT) {
                unsigned h0, l0, h1, l1;
                splitpair(v00, v01, h0, l0);
                splitpair(v10, v11, h1, l1);
                *(unsigned*)(Yh + (size_t)r * Dq + c) = h0;
                *(unsigned*)(Yl + (size_t)r * Dq + c) = l0;
                *(unsigned*)(Yh + (size_t)(r + 8) * Dq + c) = h1;
                *(unsigned*)(Yl + (size_t)(r + 8) * Dq + c) = l1;
            }
        }
    }
}

// ------- G_i = (1/cnt_i) * sum_{off} gelu(A_i + C_{i-off} + b1); fp16 hi/lo out -------
__global__ __launch_bounds__(256) void gelu_sum_kernel(
    const float* __restrict__ A, const float* __restrict__ Cc,
    const float* __restrict__ b1,
    __half* __restrict__ Gh, __half* __restrict__ Gl)
{
    int gid = blockIdx.x * blockDim.x + threadIdx.x;  // [0, Mq*64)
    int row = gid >> 6;
    int c8  = gid & 63;
    int i   = row & (Nq - 1);
    int nvalid = (i < WIN ? i : WIN) + 1;

    int idx4 = row * 128 + c8 * 2;
    float4 a0 = ((const float4*)A)[idx4];
    float4 a1 = ((const float4*)A)[idx4 + 1];
    float4 b0v = ((const float4*)b1)[c8 * 2];
    float4 b1v = ((const float4*)b1)[c8 * 2 + 1];
    a0.x += b0v.x; a0.y += b0v.y; a0.z += b0v.z; a0.w += b0v.w;
    a1.x += b1v.x; a1.y += b1v.y; a1.z += b1v.z; a1.w += b1v.w;

    float s0 = 0.f, s1 = 0.f, s2 = 0.f, s3 = 0.f;
    float s4 = 0.f, s5 = 0.f, s6 = 0.f, s7 = 0.f;
    const float4* Cp = (const float4*)Cc + idx4;
    for (int off = 0; off < nvalid; off++) {
        float4 c0 = Cp[0];
        float4 c1 = Cp[1];
        Cp -= 128;
        s0 += gelu_exact(a0.x + c0.x);
        s1 += gelu_exact(a0.y + c0.y);
        s2 += gelu_exact(a0.z + c0.z);
        s3 += gelu_exact(a0.w + c0.w);
        s4 += gelu_exact(a1.x + c1.x);
        s5 += gelu_exact(a1.y + c1.y);
        s6 += gelu_exact(a1.z + c1.z);
        s7 += gelu_exact(a1.w + c1.w);
    }
    float inv = 1.0f / (float)nvalid;
    unsigned h0, l0, h1, l1, h2, l2, h3, l3;
    splitpair(s0 * inv, s1 * inv, h0, l0);
    splitpair(s2 * inv, s3 * inv, h1, l1);
    splitpair(s4 * inv, s5 * inv, h2, l2);
    splitpair(s6 * inv, s7 * inv, h3, l3);
    uint4 hv; hv.x = h0; hv.y = h1; hv.z = h2; hv.w = h3;
    uint4 lv; lv.x = l0; lv.y = l1; lv.z = l2; lv.w = l3;
    ((uint4*)Gh)[gid] = hv;
    ((uint4*)Gl)[gid] = lv;
}

// ------------- out = LayerNorm(x) * g + b  (+ optional fp16 split) -------------
__global__ __launch_bounds__(128) void add_ln_kernel(
    const float* __restrict__ xin,
    const float* __restrict__ gw, const float* __restrict__ bw,
    float* __restrict__ out,
    __half* __restrict__ outh, __half* __restrict__ outl)
{
    int row = blockIdx.x;
    int t = threadIdx.x;
    float4 xv = ((const float4*)(xin + (size_t)row * Dq))[t];
    float x0 = xv.x, x1 = xv.y, x2 = xv.z, x3 = xv.w;

    float s  = x0 + x1 + x2 + x3;
    float ss = x0 * x0 + x1 * x1 + x2 * x2 + x3 * x3;
    #pragma unroll
    for (int o = 16; o > 0; o >>= 1) {
        s  += __shfl_xor_sync(0xffffffff, s,  o);
        ss += __shfl_xor_sync(0xffffffff, ss, o);
    }
    __shared__ float sums[4], ssums[4];
    int w = t >> 5;
    if ((t & 31) == 0) { sums[w] = s; ssums[w] = ss; }
    __syncthreads();
    float stot  = sums[0]  + sums[1]  + sums[2]  + sums[3];
    float sstot = ssums[0] + ssums[1] + ssums[2] + ssums[3];
    float mu   = stot * (1.0f / Dq);
    float var  = sstot * (1.0f / Dq) - mu * mu;
    float rstd = rsqrtf(var + 1e-5f);

    float4 gv = ((const float4*)gw)[t];
    float4 bv = ((const float4*)bw)[t];
    float4 o;
    o.x = (x0 - mu) * rstd * gv.x + bv.x;
    o.y = (x1 - mu) * rstd * gv.y + bv.y;
    o.z = (x2 - mu) * rstd * gv.z + bv.z;
    o.w = (x3 - mu) * rstd * gv.w + bv.w;
    ((float4*)(out + (size_t)row * Dq))[t] = o;
    if (outh) {
        unsigned h0, l0, h1, l1;
        splitpair(o.x, o.y, h0, l0);
        splitpair(o.z, o.w, h1, l1);
        size_t idx = (size_t)row * (Dq / 4) + t;
        uint2 hh; hh.x = h0; hh.y = h1;
        uint2 ll; ll.x = l0; ll.y = l1;
        ((uint2*)outh)[idx] = hh;
        ((uint2*)outl)[idx] = ll;
    }
}

// ---------------------------------------------------------------------------------
extern "C" void kernel_launch(void* const* d_in, const int* in_sizes, int n_in,
                              void* d_out, int out_size)
{
    const float* cs     = (const float*)d_in[0];
    const float* msg_w1 = (const float*)d_in[1];
    const float* msg_b1 = (const float*)d_in[2];
    const float* msg_w2 = (const float*)d_in[3];
    const float* msg_b2 = (const float*)d_in[4];
    const float* upd_w1 = (const float*)d_in[5];
    const float* upd_b1 = (const float*)d_in[6];
    const float* upd_w2 = (const float*)d_in[7];
    const float* upd_b2 = (const float*)d_in[8];
    const float* ln_g   = (const float*)d_in[9];
    const float* ln_b   = (const float*)d_in[10];

    float *A = 0, *C = 0, *x = 0, *h = 0, *bc = 0;
    __half *hh = 0, *hl = 0, *Gh = 0, *Gl = 0,
           *preh = 0, *prel = 0, *Wp = 0, *m2 = 0, *Wc = 0;
    if (cudaGetSymbolAddress((void**)&A,     g_A)     != cudaSuccess) return;
    if (cudaGetSymbolAddress((void**)&C,     g_C)     != cudaSuccess) return;
    if (cudaGetSymbolAddress((void**)&x,     g_x)     != cudaSuccess) return;
    if (cudaGetSymbolAddress((void**)&h,     g_h)     != cudaSuccess) return;
    if (cudaGetSymbolAddress((void**)&bc,    g_bc)    != cudaSuccess) return;
    if (cudaGetSymbolAddress((void**)&hh,    g_hh)    != cudaSuccess) return;
    if (cudaGetSymbolAddress((void**)&hl,    g_hl)    != cudaSuccess) return;
    if (cudaGetSymbolAddress((void**)&Gh,    g_Gh)    != cudaSuccess) return;
    if (cudaGetSymbolAddress((void**)&Gl,    g_Gl)    != cudaSuccess) return;
    if (cudaGetSymbolAddress((void**)&preh,  g_preh)  != cudaSuccess) return;
    if (cudaGetSymbolAddress((void**)&prel,  g_prel)  != cudaSuccess) return;
    if (cudaGetSymbolAddress((void**)&Wp,    g_Wp)    != cudaSuccess) return;
    if (cudaGetSymbolAddress((void**)&m2,    g_m2)    != cudaSuccess) return;
    if (cudaGetSymbolAddress((void**)&Wc,    g_Wc)    != cudaSuccess) return;

    cudaFuncSetAttribute(gemm_tc, cudaFuncAttributeMaxDynamicSharedMemorySize, SMEM_BYTES);

    // transposed fp16 pairs: 0=msg_w1a 1=msg_w1b 2=msg_w2(unused) 3=upd_w1a 4=upd_w1b 5=upd_w2
    prepack_kernel<<<dim3(16, 16, 6), 256>>>(
        msg_w1, msg_w1 + MATSZ, msg_w2, upd_w1, upd_w1 + MATSZ, upd_w2, Wp);

    const __half* Wm1a = Wp + (size_t)0 * 2 * MATSZ;   // hi plane (weight)
    const __half* Wm1b = Wp + (size_t)1 * 2 * MATSZ;
    const __half* Wu1a = Wp + (size_t)3 * 2 * MATSZ;
    const __half* Wu1b = Wp + (size_t)4 * 2 * MATSZ;   // hi+lo used (Wc X-operand)
    const __half* Wu2  = Wp + (size_t)5 * 2 * MATSZ;

    // row-major fp16 of msg_w2 (hi used as weight)
    split_kernel<<<MATSZ / 4 / 256, 256>>>(msg_w2, m2, m2 + MATSZ);
    // bc = upd_b1 + msg_b2 @ upd_w1b
    bias_kernel<<<16, 256>>>(msg_b2, upd_w1 + MATSZ, upd_b1, bc);
    // initial split of cs into h planes
    split_kernel<<<(Mq * Dq / 4) / 256, 256>>>(cs, hh, hl);

    dim3 blk(256);
    int gs_blocks = (Mq * 64) / 256;

    for (int r = 0; r < ROUNDS; r++) {
        const float* hin = (r == 0) ? cs : h;
        float* hout = (r == ROUNDS - 1) ? (float*)d_out : h;

        if (r == 0) {
            // fused: A = h@msg_w1a ; C = h@msg_w1b ; seg2: Wc = fp16split(upd_w1b^T @ msg_w2^T)
            gemm_tc<<<dim3(12, 64), blk, SMEM_BYTES>>>(hh, hl, Wu1b, Wu1b + MATSZ,
                Wm1a, Wm1b, m2, A, C, Wc, Wc + MATSZ,
                nullptr, nullptr, F_F32 | (F_SPLIT << 8), 16);
        } else {
            gemm_tc<<<dim3(8, 64), blk, SMEM_BYTES>>>(hh, hl, nullptr, nullptr,
                Wm1a, Wm1b, nullptr, A, C, nullptr, nullptr,
                nullptr, nullptr, F_F32, 16);
        }

        // G planes = split((1/cnt) * sum_off gelu(A + C_shift + b1))
        gelu_sum_kernel<<<gs_blocks, 256>>>(A, C, msg_b1, Gh, Gl);

        // pre planes = split(gelu([G|h] @ [Wc;upd_w1a] + bc))   K=1024
        gemm_tc<<<dim3(4, 64), blk, SMEM_BYTES>>>(Gh, Gl, hh, hl,
            Wc, nullptr, Wu1a, nullptr, nullptr,
            preh, prel, nullptr, bc, F_BIAS | F_GELU | F_SPLIT, 32);

        // x = h + pre @ upd_w2 + b2   (residual fused into epilogue)
        gemm_tc<<<dim3(4, 64), blk, SMEM_BYTES>>>(preh, prel, nullptr, nullptr,
            Wu2, nullptr, nullptr, x, nullptr,
            nullptr, nullptr, hin, upd_b2, F_ACCUM | F_BIAS | F_F32, 16);

        // h_out = LayerNorm(x)
        if (r == ROUNDS - 1)
            add_ln_kernel<<<Mq, 128>>>(x, ln_g, ln_b, hout, nullptr, nullptr);
        else
            add_ln_kernel<<<Mq, 128>>>(x, ln_g, ln_b, hout, hh, hl);
    }
}